// round 7
// baseline (speedup 1.0000x reference)
#include <cuda_runtime.h>
#include <cstddef>

// out[i] = feat[i] + (mean_k feat[nbr[i,k]]) @ W^T + b
// Factorized (mean is linear):  G = feat @ W^T + b  (GEMM, k1)
//                               out[i] = feat[nidx[i]] + mean_k G[nbr[i,k]]  (gather, k2)

static constexpr int D    = 128;
static constexpr int KDEG = 32;
static constexpr int NMAX = 100000;

__device__ __align__(16) float Wt_g[D * D];                 // Wt_g[j][d] = W[d][j]
__device__ __align__(16) float G_g[(size_t)NMAX * D];       // 51.2 MB scratch

// --- Pre-kernel: 32x32 smem-tiled transpose, both sides coalesced ---
__global__ void transpose_kernel(const float* __restrict__ W)
{
    __shared__ float tile[32][33];
    int bx = blockIdx.x & 3, by = blockIdx.x >> 2;
    int x  = bx * 32 + threadIdx.x;
    int y0 = by * 32 + threadIdx.y;
    #pragma unroll
    for (int r = 0; r < 32; r += 8)
        tile[threadIdx.y + r][threadIdx.x] = W[(y0 + r) * D + x];
    __syncthreads();
    int xo = by * 32 + threadIdx.x;
    int yo = bx * 32 + threadIdx.y;
    #pragma unroll
    for (int r = 0; r < 32; r += 8)
        Wt_g[(yo + r) * D + xo] = tile[threadIdx.x][threadIdx.y + r];
}

// ---------------- k1: G = feat @ Wt + b ----------------
// CTA: 256 threads, 64 rows. smem feat tile stride 129 (conflict-free scalar LDS).
// Warp w covers d in [16w,16w+16) for all 64 rows; lane = row within 32-group.
static constexpr int ROWS      = 64;
static constexpr int FT_STRIDE = 129;
static constexpr int K1_SMEM   = ROWS * FT_STRIDE * 4;   // 33,024 B

__global__ __launch_bounds__(256, 3)
void gemm_kernel(const float* __restrict__ feat,
                 const float* __restrict__ bias,
                 int N)
{
    extern __shared__ float ft[];
    const int tid  = threadIdx.x;
    const int lane = tid & 31;
    const int w    = tid >> 5;
    const int rowBase = blockIdx.x * ROWS;
    const float2* f2 = (const float2*)feat;

    // bias regs: bv[c] = bias[lane + 32c]
    float bv[4];
    #pragma unroll
    for (int c = 0; c < 4; c++) bv[c] = bias[lane + 32 * c];

    // ---- tile load: warp w loads rows 8w..8w+8; lane holds j-pairs {2l,2l+1},{64+2l,65+2l} ----
    #pragma unroll
    for (int rr = 0; rr < 8; rr++) {
        int rl = w * 8 + rr;
        int r  = rowBase + rl;
        float2 lo = make_float2(0.f, 0.f), hi = make_float2(0.f, 0.f);
        if (r < N) { lo = f2[(size_t)r * 64 + lane]; hi = f2[(size_t)r * 64 + 32 + lane]; }
        float* row = ft + rl * FT_STRIDE;
        row[2*lane]      = lo.x;  row[2*lane + 1]  = lo.y;
        row[64 + 2*lane] = hi.x;  row[65 + 2*lane] = hi.y;
    }
    __syncthreads();

    // ---- GEMM: per j, 2 lane-distinct scalar LDS (groups) + 4 uniform float4 W loads ----
    unsigned long long acc0[8], acc1[8];   // [d-pair 0..7] for group0/group1 rows
    #pragma unroll
    for (int p = 0; p < 8; p++) { acc0[p] = 0ull; acc1[p] = 0ull; }

    const float* a0p = ft + lane * FT_STRIDE;
    const float* a1p = ft + (32 + lane) * FT_STRIDE;
    const float* wbase = Wt_g + w * 16;

    #pragma unroll 2
    for (int j = 0; j < 128; j++) {
        float a0 = a0p[j];                       // bank l+j: conflict-free
        float a1 = a1p[j];
        const float4* wr = (const float4*)(wbase + j * D);   // warp-uniform
        float4 w0 = wr[0], w1 = wr[1], w2 = wr[2], w3 = wr[3];
        unsigned long long wp[8];
        wp[0] = *(unsigned long long*)&w0.x; wp[1] = *(unsigned long long*)&w0.z;
        wp[2] = *(unsigned long long*)&w1.x; wp[3] = *(unsigned long long*)&w1.z;
        wp[4] = *(unsigned long long*)&w2.x; wp[5] = *(unsigned long long*)&w2.z;
        wp[6] = *(unsigned long long*)&w3.x; wp[7] = *(unsigned long long*)&w3.z;
        unsigned long long ad0, ad1;
        asm("mov.b64 %0, {%1, %1};" : "=l"(ad0) : "f"(a0));
        asm("mov.b64 %0, {%1, %1};" : "=l"(ad1) : "f"(a1));
        #pragma unroll
        for (int p = 0; p < 8; p++) {
            asm("fma.rn.f32x2 %0, %1, %2, %3;" : "=l"(acc0[p]) : "l"(wp[p]), "l"(ad0), "l"(acc0[p]));
            asm("fma.rn.f32x2 %0, %1, %2, %3;" : "=l"(acc1[p]) : "l"(wp[p]), "l"(ad1), "l"(acc1[p]));
        }
    }
    __syncthreads();   // all reads of ft done -> safe to overwrite as staging

    // ---- stage results: ft[row][16w + 2p(+1)]  (banks l+16w+2p: conflict-free) ----
    {
        float* r0 = ft + lane * FT_STRIDE + w * 16;
        float* r1 = ft + (32 + lane) * FT_STRIDE + w * 16;
        #pragma unroll
        for (int p = 0; p < 8; p++) {
            float2 v0 = *(float2*)&acc0[p];
            float2 v1 = *(float2*)&acc1[p];
            r0[2*p] = v0.x; r0[2*p + 1] = v0.y;
            r1[2*p] = v1.x; r1[2*p + 1] = v1.y;
        }
    }
    __syncthreads();

    // ---- coalesced writeback + bias: warp w writes rows 8w..8w+8 ----
    #pragma unroll
    for (int rr = 0; rr < 8; rr++) {
        int rl = w * 8 + rr;
        int r  = rowBase + rl;
        if (r < N) {
            const float* row = ft + rl * FT_STRIDE;
            float* gp = G_g + (size_t)r * D;
            #pragma unroll
            for (int c = 0; c < 4; c++)
                gp[lane + 32 * c] = row[lane + 32 * c] + bv[c];   // LDS bank rl+l+0: clean
        }
    }
}

// ---------------- k2: out[i] = feat[nidx[i]] + mean_k G[nbr[i,k]] ----------------
// 1 node per warp, 8 nodes per CTA. No smem -> max occupancy.
__global__ __launch_bounds__(256)
void gather_kernel(const float* __restrict__ feat,
                   const int* __restrict__ nbr,
                   const int* __restrict__ nidx,
                   float* __restrict__ out,
                   int N)
{
    const int lane = threadIdx.x & 31;
    const int w    = threadIdx.x >> 5;
    const int node = blockIdx.x * 8 + w;
    if (node >= N) return;

    const int4* np = (const int4*)(nbr + (size_t)node * KDEG);
    const float2* g2 = (const float2*)G_g;

    float2 lo = make_float2(0.f, 0.f), hi = make_float2(0.f, 0.f);
    #pragma unroll
    for (int k4 = 0; k4 < 8; k4++) {
        int4 i = np[k4];                      // uniform per warp
        float2 t; size_t b;
        b = (size_t)i.x * 64 + lane; t = g2[b]; lo.x+=t.x; lo.y+=t.y; t = g2[b+32]; hi.x+=t.x; hi.y+=t.y;
        b = (size_t)i.y * 64 + lane; t = g2[b]; lo.x+=t.x; lo.y+=t.y; t = g2[b+32]; hi.x+=t.x; hi.y+=t.y;
        b = (size_t)i.z * 64 + lane; t = g2[b]; lo.x+=t.x; lo.y+=t.y; t = g2[b+32]; hi.x+=t.x; hi.y+=t.y;
        b = (size_t)i.w * 64 + lane; t = g2[b]; lo.x+=t.x; lo.y+=t.y; t = g2[b+32]; hi.x+=t.x; hi.y+=t.y;
    }

    const float s = 1.0f / 32.0f;
    int r = __ldg(nidx + node);
    const float2* f2 = (const float2*)feat;
    float2 flo = f2[(size_t)r * 64 + lane];
    float2 fhi = f2[(size_t)r * 64 + 32 + lane];

    float2* o2 = (float2*)out;
    o2[(size_t)node * 64 + lane]      = make_float2(lo.x * s + flo.x, lo.y * s + flo.y);
    o2[(size_t)node * 64 + 32 + lane] = make_float2(hi.x * s + fhi.x, hi.y * s + fhi.y);
}

extern "C" void kernel_launch(void* const* d_in, const int* in_sizes, int n_in,
                              void* d_out, int out_size)
{
    const float* feat = (const float*)d_in[0];
    const int*   nbr  = (const int*)d_in[1];
    const int*   nidx = (const int*)d_in[2];
    const float* W    = (const float*)d_in[3];
    const float* bias = (const float*)d_in[4];
    float*       out  = (float*)d_out;

    const int N = in_sizes[2];

    transpose_kernel<<<16, dim3(32, 8)>>>(W);

    cudaFuncSetAttribute(gemm_kernel,
                         cudaFuncAttributeMaxDynamicSharedMemorySize, K1_SMEM);
    gemm_kernel<<<(N + ROWS - 1) / ROWS, 256, K1_SMEM>>>(feat, bias, N);

    gather_kernel<<<(N + 7) / 8, 256>>>(feat, nbr, nidx, out, N);
}

// round 9
// speedup vs baseline: 1.3740x; 1.3740x over previous
#include <cuda_runtime.h>
#include <cuda_bf16.h>
#include <cstddef>

// out[i] = feat[i] + (mean_k feat[nbr[i,k]]) @ W^T + b
// Fused R6 structure; gather reads a bf16 copy of feat (halves L2 gather bytes,
// which was the binding LTS-cap bottleneck). All accumulation in fp32.

#define THREADS 256
static constexpr int D    = 128;
static constexpr int KDEG = 32;
static constexpr int NPB  = 64;      // nodes per block
static constexpr int NMAX = 100000;

static constexpr int AGG_STRIDE = 132;                 // float4-aligned rows
static constexpr int AGG_FLOATS = NPB * AGG_STRIDE;
static constexpr int SMEM_BYTES = (AGG_FLOATS + 128) * 4;   // 34,304 B -> 4 CTAs/SM

__device__ __align__(16) float          Wt_g[D * D];            // Wt_g[j][d] = W[d][j]
__device__ __align__(16) __nv_bfloat16  featb_g[(size_t)NMAX * D];  // 25.6 MB

// --- Pre-kernel 1: 32x32 smem-tiled transpose of W ---
__global__ void transpose_kernel(const float* __restrict__ W)
{
    __shared__ float tile[32][33];
    int bx = blockIdx.x & 3, by = blockIdx.x >> 2;
    int x  = bx * 32 + threadIdx.x;
    int y0 = by * 32 + threadIdx.y;
    #pragma unroll
    for (int r = 0; r < 32; r += 8)
        tile[threadIdx.y + r][threadIdx.x] = W[(y0 + r) * D + x];
    __syncthreads();
    int xo = by * 32 + threadIdx.x;
    int yo = bx * 32 + threadIdx.y;
    #pragma unroll
    for (int r = 0; r < 32; r += 8)
        Wt_g[(yo + r) * D + xo] = tile[threadIdx.x][threadIdx.y + r];
}

// --- Pre-kernel 2: feat (fp32) -> featb_g (bf16), vectorized ---
__global__ void convert_kernel(const float* __restrict__ feat, int total4)
{
    int i = blockIdx.x * blockDim.x + threadIdx.x;
    if (i < total4) {
        float4 v = ((const float4*)feat)[i];
        __nv_bfloat162 lo = __float22bfloat162_rn(make_float2(v.x, v.y));
        __nv_bfloat162 hi = __float22bfloat162_rn(make_float2(v.z, v.w));
        ((uint2*)featb_g)[i] = make_uint2(*(unsigned*)&lo, *(unsigned*)&hi);
    }
}

__global__ __launch_bounds__(THREADS, 4)
void subgconv_kernel(const float* __restrict__ feat,
                     const int* __restrict__ nbr,
                     const int* __restrict__ nidx,
                     const float* __restrict__ bias,
                     float* __restrict__ out,
                     int N)
{
    extern __shared__ float smem[];
    float* agg = smem;                   // [NPB][AGG_STRIDE]
    float* b_s = smem + AGG_FLOATS;      // [128]

    const int tid  = threadIdx.x;
    const int lane = tid & 31;
    const int w    = tid >> 5;           // warp 0..7

    if (tid < D) b_s[tid] = bias[tid];

    const int gbase = blockIdx.x * NPB;
    const unsigned* gb = (const unsigned*)featb_g;   // bf16x2 units; row = 64 units

    // ---- Phase A: warp w gathers+averages nodes gbase + w*8 .. +8 (pairs for MLP) ----
    #pragma unroll
    for (int nn = 0; nn < 8; nn += 2) {
        int n0 = gbase + w * 8 + nn;
        int n1 = n0 + 1;
        bool v0 = n0 < N, v1 = n1 < N;
        const int4* np0 = (const int4*)(nbr + (size_t)(v0 ? n0 : 0) * KDEG);
        const int4* np1 = (const int4*)(nbr + (size_t)(v1 ? n1 : 0) * KDEG);
        float2 a0l = make_float2(0.f,0.f), a0h = make_float2(0.f,0.f);
        float2 a1l = make_float2(0.f,0.f), a1h = make_float2(0.f,0.f);
        #pragma unroll 4
        for (int k4 = 0; k4 < 8; k4++) {
            int4 i0 = np0[k4];
            int4 i1 = np1[k4];
            unsigned u; float2 t; size_t b;
            #define ACC(idx, al, ah)                                                   \
                b = (size_t)(idx) * 64 + lane;                                          \
                u = gb[b];      t = __bfloat1622float2(*(__nv_bfloat162*)&u);           \
                al.x += t.x; al.y += t.y;                                               \
                u = gb[b + 32]; t = __bfloat1622float2(*(__nv_bfloat162*)&u);           \
                ah.x += t.x; ah.y += t.y;
            ACC(i0.x, a0l, a0h)  ACC(i1.x, a1l, a1h)
            ACC(i0.y, a0l, a0h)  ACC(i1.y, a1l, a1h)
            ACC(i0.z, a0l, a0h)  ACC(i1.z, a1l, a1h)
            ACC(i0.w, a0l, a0h)  ACC(i1.w, a1l, a1h)
            #undef ACC
        }
        const float s = 1.0f / 32.0f;
        if (v0) {
            float* r = agg + (w*8+nn) * AGG_STRIDE;
            *(float2*)(r + 2*lane)      = make_float2(a0l.x*s, a0l.y*s);
            *(float2*)(r + 64 + 2*lane) = make_float2(a0h.x*s, a0h.y*s);
        }
        if (v1) {
            float* r = agg + (w*8+nn+1) * AGG_STRIDE;
            *(float2*)(r + 2*lane)      = make_float2(a1l.x*s, a1l.y*s);
            *(float2*)(r + 64 + 2*lane) = make_float2(a1h.x*s, a1h.y*s);
        }
    }
    __syncthreads();

    // ---- Phase B: all 8 warps; warp w computes 128d x 8n (nodes w*8..+8).
    // Thread tile 4d x 8n, d = 4*lane..+4; W rows from L1-resident Wt_g. ----
    {
        unsigned long long acc0[8], acc1[8];
        #pragma unroll
        for (int n = 0; n < 8; n++) { acc0[n] = 0ull; acc1[n] = 0ull; }

        const float* aggb = agg + (w * 8) * AGG_STRIDE;
        const float* wcol = Wt_g + lane * 4;

        #pragma unroll 1
        for (int j4 = 0; j4 < 32; j4++) {
            float4 wv0 = *(const float4*)(wcol + (4*j4+0) * D);
            float4 wv1 = *(const float4*)(wcol + (4*j4+1) * D);
            float4 wv2 = *(const float4*)(wcol + (4*j4+2) * D);
            float4 wv3 = *(const float4*)(wcol + (4*j4+3) * D);
            unsigned long long w0a = *(unsigned long long*)&wv0.x, w0b = *(unsigned long long*)&wv0.z;
            unsigned long long w1a = *(unsigned long long*)&wv1.x, w1b = *(unsigned long long*)&wv1.z;
            unsigned long long w2a = *(unsigned long long*)&wv2.x, w2b = *(unsigned long long*)&wv2.z;
            unsigned long long w3a = *(unsigned long long*)&wv3.x, w3b = *(unsigned long long*)&wv3.z;

            #pragma unroll
            for (int n = 0; n < 8; n++) {
                float4 av = *(const float4*)(aggb + n * AGG_STRIDE + 4*j4);  // broadcast, 1 wf
                unsigned long long ad;
                asm("mov.b64 %0, {%1, %1};" : "=l"(ad) : "f"(av.x));
                asm("fma.rn.f32x2 %0, %1, %2, %3;" : "=l"(acc0[n]) : "l"(w0a), "l"(ad), "l"(acc0[n]));
                asm("fma.rn.f32x2 %0, %1, %2, %3;" : "=l"(acc1[n]) : "l"(w0b), "l"(ad), "l"(acc1[n]));
                asm("mov.b64 %0, {%1, %1};" : "=l"(ad) : "f"(av.y));
                asm("fma.rn.f32x2 %0, %1, %2, %3;" : "=l"(acc0[n]) : "l"(w1a), "l"(ad), "l"(acc0[n]));
                asm("fma.rn.f32x2 %0, %1, %2, %3;" : "=l"(acc1[n]) : "l"(w1b), "l"(ad), "l"(acc1[n]));
                asm("mov.b64 %0, {%1, %1};" : "=l"(ad) : "f"(av.z));
                asm("fma.rn.f32x2 %0, %1, %2, %3;" : "=l"(acc0[n]) : "l"(w2a), "l"(ad), "l"(acc0[n]));
                asm("fma.rn.f32x2 %0, %1, %2, %3;" : "=l"(acc1[n]) : "l"(w2b), "l"(ad), "l"(acc1[n]));
                asm("mov.b64 %0, {%1, %1};" : "=l"(ad) : "f"(av.w));
                asm("fma.rn.f32x2 %0, %1, %2, %3;" : "=l"(acc0[n]) : "l"(w3a), "l"(ad), "l"(acc0[n]));
                asm("fma.rn.f32x2 %0, %1, %2, %3;" : "=l"(acc1[n]) : "l"(w3b), "l"(ad), "l"(acc1[n]));
            }
        }

        // Epilogue: out[node][4l..4l+4) = acc + feat[nidx[node]] + b   (fp32 exact residual)
        float4 bv = *(const float4*)&b_s[lane * 4];
        const int nbase = gbase + w * 8;
        #pragma unroll
        for (int n = 0; n < 8; n++) {
            int node = nbase + n;
            if (node < N) {
                int r = nidx[node];
                float4 fv = ((const float4*)feat)[(size_t)r * 32 + lane];
                float2 p0 = *(float2*)&acc0[n];
                float2 p1 = *(float2*)&acc1[n];
                float4 o = make_float4(p0.x + fv.x + bv.x, p0.y + fv.y + bv.y,
                                       p1.x + fv.z + bv.z, p1.y + fv.w + bv.w);
                ((float4*)out)[(size_t)node * 32 + lane] = o;
            }
        }
    }
}

extern "C" void kernel_launch(void* const* d_in, const int* in_sizes, int n_in,
                              void* d_out, int out_size)
{
    const float* feat = (const float*)d_in[0];
    const int*   nbr  = (const int*)d_in[1];
    const int*   nidx = (const int*)d_in[2];
    const float* W    = (const float*)d_in[3];
    const float* bias = (const float*)d_in[4];
    float*       out  = (float*)d_out;

    const int N = in_sizes[2];

    transpose_kernel<<<16, dim3(32, 8)>>>(W);

    const int total4 = (N * D) / 4;
    convert_kernel<<<(total4 + 255) / 256, 256>>>(feat, total4);

    cudaFuncSetAttribute(subgconv_kernel,
                         cudaFuncAttributeMaxDynamicSharedMemorySize, SMEM_BYTES);
    const int grid = (N + NPB - 1) / NPB;
    subgconv_kernel<<<grid, THREADS, SMEM_BYTES>>>(feat, nbr, nidx, bias, out, N);
}

// round 10
// speedup vs baseline: 1.4643x; 1.0658x over previous
#include <cuda_runtime.h>
#include <cstddef>

// out[i] = feat[i] + (mean_k feat[nbr[i,k]]) @ W^T + b
// N=100000, D=128, K=32, int32 idx. Fused fp32 kernel, latency-optimized:
// 128-thread CTAs, NPB=32 -> 8 CTAs/SM (8 independent phase pipelines),
// LDG.128 gather (half the gather instructions), f32x2 phase-B GEMM.

#define THREADS 128
static constexpr int D    = 128;
static constexpr int KDEG = 32;
static constexpr int NPB  = 32;      // nodes per block

static constexpr int AGG_STRIDE = 132;                 // float4-aligned rows
static constexpr int AGG_FLOATS = NPB * AGG_STRIDE;
static constexpr int SMEM_BYTES = (AGG_FLOATS + 128) * 4;   // 17,408 B -> 8 CTAs/SM

__device__ __align__(16) float Wt_g[D * D];   // Wt_g[j][d] = W[d][j]

// --- Pre-kernel: 32x32 smem-tiled transpose of W ---
__global__ void transpose_kernel(const float* __restrict__ W)
{
    __shared__ float tile[32][33];
    int bx = blockIdx.x & 3, by = blockIdx.x >> 2;
    int x  = bx * 32 + threadIdx.x;
    int y0 = by * 32 + threadIdx.y;
    #pragma unroll
    for (int r = 0; r < 32; r += 8)
        tile[threadIdx.y + r][threadIdx.x] = W[(y0 + r) * D + x];
    __syncthreads();
    int xo = by * 32 + threadIdx.x;
    int yo = bx * 32 + threadIdx.y;
    #pragma unroll
    for (int r = 0; r < 32; r += 8)
        Wt_g[(yo + r) * D + xo] = tile[threadIdx.x][threadIdx.y + r];
}

__global__ __launch_bounds__(THREADS, 8)
void subgconv_kernel(const float* __restrict__ feat,
                     const int* __restrict__ nbr,
                     const int* __restrict__ nidx,
                     const float* __restrict__ bias,
                     float* __restrict__ out,
                     int N)
{
    extern __shared__ float smem[];
    float* agg = smem;                   // [NPB][AGG_STRIDE]
    float* b_s = smem + AGG_FLOATS;      // [128]

    const int tid  = threadIdx.x;
    const int lane = tid & 31;
    const int w    = tid >> 5;           // warp 0..3

    b_s[tid] = bias[tid];

    const int gbase = blockIdx.x * NPB;
    const float4* f4 = (const float4*)feat;

    // ---- Phase A: warp w gathers+averages nodes gbase + w*8 .. +8 (pairs for MLP) ----
    #pragma unroll
    for (int nn = 0; nn < 8; nn += 2) {
        int n0 = gbase + w * 8 + nn;
        int n1 = n0 + 1;
        bool v0 = n0 < N, v1 = n1 < N;
        const int4* np0 = (const int4*)(nbr + (size_t)(v0 ? n0 : 0) * KDEG);
        const int4* np1 = (const int4*)(nbr + (size_t)(v1 ? n1 : 0) * KDEG);
        float4 a0 = make_float4(0.f,0.f,0.f,0.f);
        float4 a1 = make_float4(0.f,0.f,0.f,0.f);
        #pragma unroll 4
        for (int k4 = 0; k4 < 8; k4++) {
            int4 i0 = np0[k4];
            int4 i1 = np1[k4];
            float4 t;
            t = f4[(size_t)i0.x*32 + lane]; a0.x+=t.x; a0.y+=t.y; a0.z+=t.z; a0.w+=t.w;
            t = f4[(size_t)i1.x*32 + lane]; a1.x+=t.x; a1.y+=t.y; a1.z+=t.z; a1.w+=t.w;
            t = f4[(size_t)i0.y*32 + lane]; a0.x+=t.x; a0.y+=t.y; a0.z+=t.z; a0.w+=t.w;
            t = f4[(size_t)i1.y*32 + lane]; a1.x+=t.x; a1.y+=t.y; a1.z+=t.z; a1.w+=t.w;
            t = f4[(size_t)i0.z*32 + lane]; a0.x+=t.x; a0.y+=t.y; a0.z+=t.z; a0.w+=t.w;
            t = f4[(size_t)i1.z*32 + lane]; a1.x+=t.x; a1.y+=t.y; a1.z+=t.z; a1.w+=t.w;
            t = f4[(size_t)i0.w*32 + lane]; a0.x+=t.x; a0.y+=t.y; a0.z+=t.z; a0.w+=t.w;
            t = f4[(size_t)i1.w*32 + lane]; a1.x+=t.x; a1.y+=t.y; a1.z+=t.z; a1.w+=t.w;
        }
        const float s = 1.0f / 32.0f;
        if (v0)
            *(float4*)&agg[(w*8+nn  ) * AGG_STRIDE + 4*lane] =
                make_float4(a0.x*s, a0.y*s, a0.z*s, a0.w*s);
        if (v1)
            *(float4*)&agg[(w*8+nn+1) * AGG_STRIDE + 4*lane] =
                make_float4(a1.x*s, a1.y*s, a1.z*s, a1.w*s);
    }
    __syncthreads();

    // ---- Phase B: warp w computes 128d x 8n (nodes w*8..+8).
    // Thread tile 4d x 8n, d = 4*lane..+4; W rows from L1-resident Wt_g. ----
    {
        unsigned long long acc0[8], acc1[8];
        #pragma unroll
        for (int n = 0; n < 8; n++) { acc0[n] = 0ull; acc1[n] = 0ull; }

        const float* aggb = agg + (w * 8) * AGG_STRIDE;
        const float* wcol = Wt_g + lane * 4;

        #pragma unroll 1
        for (int j4 = 0; j4 < 32; j4++) {
            float4 wv0 = *(const float4*)(wcol + (4*j4+0) * D);
            float4 wv1 = *(const float4*)(wcol + (4*j4+1) * D);
            float4 wv2 = *(const float4*)(wcol + (4*j4+2) * D);
            float4 wv3 = *(const float4*)(wcol + (4*j4+3) * D);
            unsigned long long w0a = *(unsigned long long*)&wv0.x, w0b = *(unsigned long long*)&wv0.z;
            unsigned long long w1a = *(unsigned long long*)&wv1.x, w1b = *(unsigned long long*)&wv1.z;
            unsigned long long w2a = *(unsigned long long*)&wv2.x, w2b = *(unsigned long long*)&wv2.z;
            unsigned long long w3a = *(unsigned long long*)&wv3.x, w3b = *(unsigned long long*)&wv3.z;

            #pragma unroll
            for (int n = 0; n < 8; n++) {
                float4 av = *(const float4*)(aggb + n * AGG_STRIDE + 4*j4);  // broadcast, 1 wf
                unsigned long long ad;
                asm("mov.b64 %0, {%1, %1};" : "=l"(ad) : "f"(av.x));
                asm("fma.rn.f32x2 %0, %1, %2, %3;" : "=l"(acc0[n]) : "l"(w0a), "l"(ad), "l"(acc0[n]));
                asm("fma.rn.f32x2 %0, %1, %2, %3;" : "=l"(acc1[n]) : "l"(w0b), "l"(ad), "l"(acc1[n]));
                asm("mov.b64 %0, {%1, %1};" : "=l"(ad) : "f"(av.y));
                asm("fma.rn.f32x2 %0, %1, %2, %3;" : "=l"(acc0[n]) : "l"(w1a), "l"(ad), "l"(acc0[n]));
                asm("fma.rn.f32x2 %0, %1, %2, %3;" : "=l"(acc1[n]) : "l"(w1b), "l"(ad), "l"(acc1[n]));
                asm("mov.b64 %0, {%1, %1};" : "=l"(ad) : "f"(av.z));
                asm("fma.rn.f32x2 %0, %1, %2, %3;" : "=l"(acc0[n]) : "l"(w2a), "l"(ad), "l"(acc0[n]));
                asm("fma.rn.f32x2 %0, %1, %2, %3;" : "=l"(acc1[n]) : "l"(w2b), "l"(ad), "l"(acc1[n]));
                asm("mov.b64 %0, {%1, %1};" : "=l"(ad) : "f"(av.w));
                asm("fma.rn.f32x2 %0, %1, %2, %3;" : "=l"(acc0[n]) : "l"(w3a), "l"(ad), "l"(acc0[n]));
                asm("fma.rn.f32x2 %0, %1, %2, %3;" : "=l"(acc1[n]) : "l"(w3b), "l"(ad), "l"(acc1[n]));
            }
        }

        // Epilogue: out[node][4l..4l+4) = acc + feat[nidx[node]] + b
        float4 bv = *(const float4*)&b_s[lane * 4];
        const int nbase = gbase + w * 8;
        #pragma unroll
        for (int n = 0; n < 8; n++) {
            int node = nbase + n;
            if (node < N) {
                int r = nidx[node];
                float4 fv = f4[(size_t)r * 32 + lane];
                float2 p0 = *(float2*)&acc0[n];
                float2 p1 = *(float2*)&acc1[n];
                float4 o = make_float4(p0.x + fv.x + bv.x, p0.y + fv.y + bv.y,
                                       p1.x + fv.z + bv.z, p1.y + fv.w + bv.w);
                ((float4*)out)[(size_t)node * 32 + lane] = o;
            }
        }
    }
}

extern "C" void kernel_launch(void* const* d_in, const int* in_sizes, int n_in,
                              void* d_out, int out_size)
{
    const float* feat = (const float*)d_in[0];
    const int*   nbr  = (const int*)d_in[1];
    const int*   nidx = (const int*)d_in[2];
    const float* W    = (const float*)d_in[3];
    const float* bias = (const float*)d_in[4];
    float*       out  = (float*)d_out;

    const int N = in_sizes[2];

    transpose_kernel<<<16, dim3(32, 8)>>>(W);

    cudaFuncSetAttribute(subgconv_kernel,
                         cudaFuncAttributeMaxDynamicSharedMemorySize, SMEM_BYTES);
    const int grid = (N + NPB - 1) / NPB;
    subgconv_kernel<<<grid, THREADS, SMEM_BYTES>>>(feat, nbr, nidx, bias, out, N);
}

// round 11
// speedup vs baseline: 1.7218x; 1.1759x over previous
#include <cuda_runtime.h>
#include <cstddef>

// out[i] = feat[i] + (mean_k feat[nbr[i,k]]) @ W^T + b
// N=100000, D=128, K=32, int32 idx.
// Phase A: LDG.64 gather + f32x2 accumulate -> tf32-rounded agg in smem.
// Phase B: tf32 mma.sync.m16n8k8 (A=agg smem, B=Wt_g global/L1-resident).
// D round-trips through the agg buffer for a coalesced epilogue.

#define THREADS 128
static constexpr int D    = 128;
static constexpr int KDEG = 32;
static constexpr int NPB  = 32;

static constexpr int AGG_STRIDE = 132;   // bank(4m+kc)=lane -> conflict-free A frags
static constexpr int AGG_FLOATS = NPB * AGG_STRIDE;
static constexpr int SMEM_BYTES = (AGG_FLOATS + 128) * 4;   // 17,408 B

__device__ __align__(16) float Wt_g[D * D];   // tf32-rounded W^T: Wt_g[j][d] = W[d][j]

// --- Pre-kernel: transpose W and round to tf32 ---
__global__ void transpose_kernel(const float* __restrict__ W)
{
    __shared__ float tile[32][33];
    int bx = blockIdx.x & 3, by = blockIdx.x >> 2;
    int x  = bx * 32 + threadIdx.x;
    int y0 = by * 32 + threadIdx.y;
    #pragma unroll
    for (int r = 0; r < 32; r += 8)
        tile[threadIdx.y + r][threadIdx.x] = W[(y0 + r) * D + x];
    __syncthreads();
    int xo = by * 32 + threadIdx.x;
    int yo = bx * 32 + threadIdx.y;
    #pragma unroll
    for (int r = 0; r < 32; r += 8) {
        float v = tile[threadIdx.x][threadIdx.y + r];
        unsigned u;
        asm("cvt.rna.tf32.f32 %0, %1;" : "=r"(u) : "f"(v));
        Wt_g[(yo + r) * D + xo] = __uint_as_float(u);
    }
}

__device__ __forceinline__ void addx2(unsigned long long& a, unsigned long long v) {
    asm("add.rn.f32x2 %0, %1, %2;" : "=l"(a) : "l"(v), "l"(a));
}

__device__ __forceinline__ uint2 scale_tf32(unsigned long long a) {
    const unsigned long long ss = 0x3D0000003D000000ULL;   // {1/32, 1/32}
    unsigned long long r;
    asm("mul.rn.f32x2 %0, %1, %2;" : "=l"(r) : "l"(a), "l"(ss));
    float2 f = *(float2*)&r;
    unsigned lo, hi;
    asm("cvt.rna.tf32.f32 %0, %1;" : "=r"(lo) : "f"(f.x));
    asm("cvt.rna.tf32.f32 %0, %1;" : "=r"(hi) : "f"(f.y));
    return make_uint2(lo, hi);
}

__global__ __launch_bounds__(THREADS, 8)
void subgconv_kernel(const float* __restrict__ feat,
                     const int* __restrict__ nbr,
                     const int* __restrict__ nidx,
                     const float* __restrict__ bias,
                     float* __restrict__ out,
                     int N)
{
    extern __shared__ float smem[];
    float* agg = smem;                   // [NPB][AGG_STRIDE]; later reused as Dbuf
    float* b_s = smem + AGG_FLOATS;      // [128]

    const int tid  = threadIdx.x;
    const int lane = tid & 31;
    const int w    = tid >> 5;           // warp 0..3

    b_s[tid] = bias[tid];

    const int gbase = blockIdx.x * NPB;
    const float2* f2 = (const float2*)feat;

    // ---- Phase A: warp w gathers+averages nodes gbase + w*8 .. +8 ----
    #pragma unroll
    for (int nn = 0; nn < 8; nn += 2) {
        int n0 = gbase + w * 8 + nn;
        int n1 = n0 + 1;
        bool v0 = n0 < N, v1 = n1 < N;
        const int4* np0 = (const int4*)(nbr + (size_t)(v0 ? n0 : 0) * KDEG);
        const int4* np1 = (const int4*)(nbr + (size_t)(v1 ? n1 : 0) * KDEG);
        unsigned long long a0l = 0ull, a0h = 0ull, a1l = 0ull, a1h = 0ull;
        #pragma unroll 4
        for (int k4 = 0; k4 < 8; k4++) {
            int4 i0 = np0[k4];
            int4 i1 = np1[k4];
            unsigned long long v; size_t b;
            #define ACC(idx, al, ah)                                     \
                b = (size_t)(idx) * 64 + lane;                            \
                v = *(const unsigned long long*)(f2 + b);      addx2(al, v); \
                v = *(const unsigned long long*)(f2 + b + 32); addx2(ah, v);
            ACC(i0.x, a0l, a0h)  ACC(i1.x, a1l, a1h)
            ACC(i0.y, a0l, a0h)  ACC(i1.y, a1l, a1h)
            ACC(i0.z, a0l, a0h)  ACC(i1.z, a1l, a1h)
            ACC(i0.w, a0l, a0h)  ACC(i1.w, a1l, a1h)
            #undef ACC
        }
        unsigned* au = (unsigned*)agg;
        if (v0) {
            int r = (w*8+nn) * AGG_STRIDE;
            *(uint2*)(au + r + 2*lane)      = scale_tf32(a0l);
            *(uint2*)(au + r + 64 + 2*lane) = scale_tf32(a0h);
        }
        if (v1) {
            int r = (w*8+nn+1) * AGG_STRIDE;
            *(uint2*)(au + r + 2*lane)      = scale_tf32(a1l);
            *(uint2*)(au + r + 64 + 2*lane) = scale_tf32(a1h);
        }
    }
    __syncthreads();

    // ---- Phase B: warp w covers d-slice [32w, 32w+32) x all 32 nodes, tf32 MMA ----
    {
        const int m0 = lane >> 2;      // groupID
        const int kc = lane & 3;       // threadID_in_group
        const int dw = w * 32;

        float c[2][4][4];
        #pragma unroll
        for (int mt = 0; mt < 2; mt++)
            #pragma unroll
            for (int nt = 0; nt < 4; nt++)
                #pragma unroll
                for (int i = 0; i < 4; i++) c[mt][nt][i] = 0.f;

        const unsigned* aggu = (const unsigned*)agg;
        const int abase = m0 * AGG_STRIDE + kc;
        const float* bbase = Wt_g + kc * D + dw + m0;

        #pragma unroll 1
        for (int k8 = 0; k8 < 16; k8++) {
            const unsigned* ak = aggu + abase + k8 * 8;
            unsigned a[2][4];
            #pragma unroll
            for (int mt = 0; mt < 2; mt++) {
                int mo = mt * 16 * AGG_STRIDE;
                a[mt][0] = ak[mo];
                a[mt][1] = ak[mo + 8 * AGG_STRIDE];
                a[mt][2] = ak[mo + 4];
                a[mt][3] = ak[mo + 8 * AGG_STRIDE + 4];
            }
            const float* bk = bbase + k8 * 8 * D;
            unsigned b[4][2];
            #pragma unroll
            for (int nt = 0; nt < 4; nt++) {
                b[nt][0] = __float_as_uint(bk[nt * 8]);
                b[nt][1] = __float_as_uint(bk[nt * 8 + 4 * D]);
            }
            #pragma unroll
            for (int mt = 0; mt < 2; mt++)
                #pragma unroll
                for (int nt = 0; nt < 4; nt++) {
                    asm volatile(
                        "mma.sync.aligned.m16n8k8.row.col.f32.tf32.tf32.f32 "
                        "{%0,%1,%2,%3}, {%4,%5,%6,%7}, {%8,%9}, {%0,%1,%2,%3};"
                        : "+f"(c[mt][nt][0]), "+f"(c[mt][nt][1]),
                          "+f"(c[mt][nt][2]), "+f"(c[mt][nt][3])
                        : "r"(a[mt][0]), "r"(a[mt][1]), "r"(a[mt][2]), "r"(a[mt][3]),
                          "r"(b[nt][0]), "r"(b[nt][1]));
                }
        }
        __syncthreads();   // all agg reads complete -> reuse buffer as Dbuf

        // D store: row = m0 + 16mt (+8), col = dw + 8nt + 2kc
        #pragma unroll
        for (int mt = 0; mt < 2; mt++)
            #pragma unroll
            for (int nt = 0; nt < 4; nt++) {
                float* dp = agg + (m0 + mt*16) * AGG_STRIDE + dw + nt*8 + 2*kc;
                *(float2*)dp                    = make_float2(c[mt][nt][0], c[mt][nt][1]);
                *(float2*)(dp + 8 * AGG_STRIDE) = make_float2(c[mt][nt][2], c[mt][nt][3]);
            }
    }
    __syncthreads();

    // ---- Epilogue: warp w writes nodes w*8..+8: out = D + feat[nidx] + b ----
    {
        float4 bv = *(const float4*)&b_s[lane * 4];
        #pragma unroll
        for (int n = 0; n < 8; n++) {
            int nl   = w * 8 + n;
            int node = gbase + nl;
            if (node < N) {
                int r = nidx[node];
                float4 dv = *(const float4*)&agg[nl * AGG_STRIDE + 4 * lane];
                float4 fv = ((const float4*)feat)[(size_t)r * 32 + lane];
                float4 o = make_float4(dv.x + fv.x + bv.x, dv.y + fv.y + bv.y,
                                       dv.z + fv.z + bv.z, dv.w + fv.w + bv.w);
                ((float4*)out)[(size_t)node * 32 + lane] = o;
            }
        }
    }
}

extern "C" void kernel_launch(void* const* d_in, const int* in_sizes, int n_in,
                              void* d_out, int out_size)
{
    const float* feat = (const float*)d_in[0];
    const int*   nbr  = (const int*)d_in[1];
    const int*   nidx = (const int*)d_in[2];
    const float* W    = (const float*)d_in[3];
    const float* bias = (const float*)d_in[4];
    float*       out  = (float*)d_out;

    const int N = in_sizes[2];

    transpose_kernel<<<16, dim3(32, 8)>>>(W);

    cudaFuncSetAttribute(subgconv_kernel,
                         cudaFuncAttributeMaxDynamicSharedMemorySize, SMEM_BYTES);
    const int grid = (N + NPB - 1) / NPB;
    subgconv_kernel<<<grid, THREADS, SMEM_BYTES>>>(feat, nbr, nidx, bias, out, N);
}

// round 14
// speedup vs baseline: 1.7558x; 1.0197x over previous
#include <cuda_runtime.h>
#include <cuda_bf16.h>
#include <cstddef>

// out[i] = feat[i] + (mean_k feat[nbr[i,k]]) @ W^T + b
// N=100000, D=128, K=32, int32 idx.
// Phase A: bf16 gather (1-line LDG.32s, halves LTS bytes) -> tf32 agg in smem.
// Phase B: tf32 mma.sync.m16n8k8; B fragments from repacked Wrep_g via 2x LDG.128.
// Residual + bias epilogue in exact fp32.

#define THREADS 128
static constexpr int D    = 128;
static constexpr int KDEG = 32;
static constexpr int NPB  = 32;
static constexpr int NMAX = 100000;

static constexpr int AGG_STRIDE = 132;   // A-frag scalar LDS bank = lane -> conflict-free
static constexpr int AGG_FLOATS = NPB * AGG_STRIDE;
static constexpr int SMEM_BYTES = (AGG_FLOATS + 128) * 4;   // 17,408 B -> 8 CTAs/SM

__device__ __align__(16) float         Wrep_g[4 * 16 * 32 * 8];       // 64 KB, frag-ordered
__device__ __align__(16) __nv_bfloat16 featb_g[(size_t)NMAX * D];     // 25.6 MB

// --- Pre-kernel 1: repack W into per-(warp,k8,lane) fragment order, tf32-rounded.
// Wrep[((w*16 + k8)*32 + lane)*8 + i*4 + nt] = tf32( W[d][j] ),
//   d = w*32 + nt*8 + (lane>>2),  j = 8*k8 + (lane&3) + 4*i.
__global__ void repack_kernel(const float* __restrict__ W)
{
    int idx = blockIdx.x * 256 + threadIdx.x;     // 0..16383
    int q    = idx & 7;
    int lane = (idx >> 3) & 31;
    int k8   = (idx >> 8) & 15;
    int w    = idx >> 12;
    int i  = q >> 2, nt = q & 3;
    int kc = lane & 3, m0 = lane >> 2;
    int j = 8 * k8 + kc + 4 * i;
    int d = w * 32 + nt * 8 + m0;
    float v = W[d * D + j];
    unsigned u;
    asm("cvt.rna.tf32.f32 %0, %1;" : "=r"(u) : "f"(v));
    Wrep_g[idx] = __uint_as_float(u);
}

// --- Pre-kernel 2: feat (fp32) -> featb_g (bf16), vectorized ---
__global__ void convert_kernel(const float* __restrict__ feat, int total4)
{
    int i = blockIdx.x * blockDim.x + threadIdx.x;
    if (i < total4) {
        float4 v = ((const float4*)feat)[i];
        __nv_bfloat162 lo = __float22bfloat162_rn(make_float2(v.x, v.y));
        __nv_bfloat162 hi = __float22bfloat162_rn(make_float2(v.z, v.w));
        ((uint2*)featb_g)[i] = make_uint2(*(unsigned*)&lo, *(unsigned*)&hi);
    }
}

__device__ __forceinline__ uint2 scale_tf32(float2 f) {
    const float s = 1.0f / 32.0f;
    unsigned lo, hi;
    float x = f.x * s, y = f.y * s;
    asm("cvt.rna.tf32.f32 %0, %1;" : "=r"(lo) : "f"(x));
    asm("cvt.rna.tf32.f32 %0, %1;" : "=r"(hi) : "f"(y));
    return make_uint2(lo, hi);
}

__global__ __launch_bounds__(THREADS, 8)
void subgconv_kernel(const float* __restrict__ feat,
                     const int* __restrict__ nbr,
                     const int* __restrict__ nidx,
                     const float* __restrict__ bias,
                     float* __restrict__ out,
                     int N)
{
    extern __shared__ float smem[];
    float* agg = smem;                   // [NPB][AGG_STRIDE]; reused as Dbuf
    float* b_s = smem + AGG_FLOATS;      // [128]

    const int tid  = threadIdx.x;
    const int lane = tid & 31;
    const int w    = tid >> 5;           // warp 0..3

    b_s[tid] = bias[tid];

    const int gbase = blockIdx.x * NPB;
    const unsigned* gb = (const unsigned*)featb_g;   // bf16x2 units; row = 64 units

    // ---- Phase A: warp w gathers+averages nodes gbase + w*8 .. +8 (bf16, pairs) ----
    #pragma unroll
    for (int nn = 0; nn < 8; nn += 2) {
        int n0 = gbase + w * 8 + nn;
        int n1 = n0 + 1;
        bool v0 = n0 < N, v1 = n1 < N;
        const int4* np0 = (const int4*)(nbr + (size_t)(v0 ? n0 : 0) * KDEG);
        const int4* np1 = (const int4*)(nbr + (size_t)(v1 ? n1 : 0) * KDEG);
        float2 a0l = make_float2(0.f,0.f), a0h = make_float2(0.f,0.f);
        float2 a1l = make_float2(0.f,0.f), a1h = make_float2(0.f,0.f);
        #pragma unroll 4
        for (int k4 = 0; k4 < 8; k4++) {
            int4 i0 = np0[k4];
            int4 i1 = np1[k4];
            unsigned u; float2 t; size_t b;
            #define ACC(idx, al, ah)                                          \
                b = (size_t)(idx) * 64 + lane;                                 \
                u = gb[b];      t = __bfloat1622float2(*(__nv_bfloat162*)&u);  \
                al.x += t.x; al.y += t.y;                                      \
                u = gb[b + 32]; t = __bfloat1622float2(*(__nv_bfloat162*)&u);  \
                ah.x += t.x; ah.y += t.y;
            ACC(i0.x, a0l, a0h)  ACC(i1.x, a1l, a1h)
            ACC(i0.y, a0l, a0h)  ACC(i1.y, a1l, a1h)
            ACC(i0.z, a0l, a0h)  ACC(i1.z, a1l, a1h)
            ACC(i0.w, a0l, a0h)  ACC(i1.w, a1l, a1h)
            #undef ACC
        }
        unsigned* au = (unsigned*)agg;
        if (v0) {
            int r = (w*8+nn) * AGG_STRIDE;
            *(uint2*)(au + r + 2*lane)      = scale_tf32(a0l);
            *(uint2*)(au + r + 64 + 2*lane) = scale_tf32(a0h);
        }
        if (v1) {
            int r = (w*8+nn+1) * AGG_STRIDE;
            *(uint2*)(au + r + 2*lane)      = scale_tf32(a1l);
            *(uint2*)(au + r + 64 + 2*lane) = scale_tf32(a1h);
        }
    }
    __syncthreads();

    // ---- Phase B: warp w covers d-slice [32w,32w+32) x 32 nodes, tf32 MMA ----
    {
        const int m0 = lane >> 2;      // groupID
        const int kc = lane & 3;       // threadID_in_group
        const int dw = w * 32;

        float c[2][4][4];
        #pragma unroll
        for (int mt = 0; mt < 2; mt++)
            #pragma unroll
            for (int nt = 0; nt < 4; nt++)
                #pragma unroll
                for (int i = 0; i < 4; i++) c[mt][nt][i] = 0.f;

        const unsigned* aggu = (const unsigned*)agg;
        const int abase = m0 * AGG_STRIDE + kc;
        const float4* wrep = (const float4*)Wrep_g + ((size_t)w * 16 * 32 + lane) * 2;

        #pragma unroll 1
        for (int k8 = 0; k8 < 16; k8++) {
            const unsigned* ak = aggu + abase + k8 * 8;
            unsigned a[2][4];
            #pragma unroll
            for (int mt = 0; mt < 2; mt++) {
                int mo = mt * 16 * AGG_STRIDE;
                a[mt][0] = ak[mo];
                a[mt][1] = ak[mo + 8 * AGG_STRIDE];
                a[mt][2] = ak[mo + 4];
                a[mt][3] = ak[mo + 8 * AGG_STRIDE + 4];
            }
            float4 f0 = wrep[k8 * 64];          // b[nt][0], nt=0..3
            float4 f1 = wrep[k8 * 64 + 1];      // b[nt][1]
            const float* b0 = &f0.x;
            const float* b1 = &f1.x;
            #pragma unroll
            for (int mt = 0; mt < 2; mt++)
                #pragma unroll
                for (int nt = 0; nt < 4; nt++) {
                    asm volatile(
                        "mma.sync.aligned.m16n8k8.row.col.f32.tf32.tf32.f32 "
                        "{%0,%1,%2,%3}, {%4,%5,%6,%7}, {%8,%9}, {%0,%1,%2,%3};"
                        : "+f"(c[mt][nt][0]), "+f"(c[mt][nt][1]),
                          "+f"(c[mt][nt][2]), "+f"(c[mt][nt][3])
                        : "r"(a[mt][0]), "r"(a[mt][1]), "r"(a[mt][2]), "r"(a[mt][3]),
                          "r"(__float_as_uint(b0[nt])), "r"(__float_as_uint(b1[nt])));
                }
        }
        __syncthreads();   // all agg reads complete -> reuse buffer as Dbuf

        // D store: row = m0 + 16mt (+8), col = dw + 8nt + 2kc
        #pragma unroll
        for (int mt = 0; mt < 2; mt++)
            #pragma unroll
            for (int nt = 0; nt < 4; nt++) {
                float* dp = agg + (m0 + mt*16) * AGG_STRIDE + dw + nt*8 + 2*kc;
                *(float2*)dp                    = make_float2(c[mt][nt][0], c[mt][nt][1]);
                *(float2*)(dp + 8 * AGG_STRIDE) = make_float2(c[mt][nt][2], c[mt][nt][3]);
            }
    }
    __syncthreads();

    // ---- Epilogue: warp w writes nodes w*8..+8: out = D + feat[nidx] + b (fp32) ----
    {
        float4 bv = *(const float4*)&b_s[lane * 4];
        #pragma unroll
        for (int n = 0; n < 8; n++) {
            int nl   = w * 8 + n;
            int node = gbase + nl;
            if (node < N) {
                int r = nidx[node];
                float4 dv = *(const float4*)&agg[nl * AGG_STRIDE + 4 * lane];
                float4 fv = ((const float4*)feat)[(size_t)r * 32 + lane];
                float4 o = make_float4(dv.x + fv.x + bv.x, dv.y + fv.y + bv.y,
                                       dv.z + fv.z + bv.z, dv.w + fv.w + bv.w);
                ((float4*)out)[(size_t)node * 32 + lane] = o;
            }
        }
    }
}

extern "C" void kernel_launch(void* const* d_in, const int* in_sizes, int n_in,
                              void* d_out, int out_size)
{
    const float* feat = (const float*)d_in[0];
    const int*   nbr  = (const int*)d_in[1];
    const int*   nidx = (const int*)d_in[2];
    const float* W    = (const float*)d_in[3];
    const float* bias = (const float*)d_in[4];
    float*       out  = (float*)d_out;

    const int N = in_sizes[2];

    repack_kernel<<<64, 256>>>(W);

    const int total4 = (N * D) / 4;
    convert_kernel<<<(total4 + 255) / 256, 256>>>(feat, total4);

    cudaFuncSetAttribute(subgconv_kernel,
                         cudaFuncAttributeMaxDynamicSharedMemorySize, SMEM_BYTES);
    const int grid = (N + NPB - 1) / NPB;
    subgconv_kernel<<<grid, THREADS, SMEM_BYTES>>>(feat, nbr, nidx, bias, out, N);
}